// round 5
// baseline (speedup 1.0000x reference)
#include <cuda_runtime.h>
#include <math_constants.h>

// Hausdorff loss: x,y (8, 4096, 3) fp32 -> scalar.
// loss_b = max over all 8192 per-query NN distances (both directions).
// Squared-distance trick + early-exit pruning:
//   pilot computes exact NN for a query subset -> lower bound L_b on loss_b.
//   main abandons any warp once ALL its queries' running mins < L_b (those
//   queries provably cannot be the argmax). Survivors scan fully -> exact.

#define NB 8        // batches
#define V 4096      // points per cloud
#define TS 2048     // targets per smem tile (float4 = 32KB)
#define THREADS 256
#define QPB 512     // queries per block (2 per thread)
#define CHUNKS (V / QPB)   // 8 -> main grid 8 x 8 x 2 = 128 CTAs

#define PQ 64       // pilot queries per (batch, dir)
#define PSTRIPES 4  // target stripes in pilot

__device__ unsigned g_max[NB];
__device__ unsigned g_L[NB];

__global__ void hd_init_kernel() {
    if (threadIdx.x < NB) { g_max[threadIdx.x] = 0u; g_L[threadIdx.x] = 0u; }
}

// ---- Pilot: exact NN^2 for 64 strided queries per (b, dir); L_b = max. ----
__global__ void __launch_bounds__(THREADS, 1)
hd_pilot_kernel(const float* __restrict__ X, const float* __restrict__ Y) {
    const int dir = blockIdx.x;
    const int b   = blockIdx.y;
    const float* __restrict__ Qp = (dir == 0 ? X : Y) + (size_t)b * V * 3;
    const float* __restrict__ Tp = (dir == 0 ? Y : X) + (size_t)b * V * 3;

    const int tid    = threadIdx.x;
    const int qi     = tid & (PQ - 1);   // 0..63
    const int stripe = tid >> 6;         // 0..3
    const int q      = qi * (V / PQ);    // strided sample

    const float qx = Qp[q * 3 + 0], qy = Qp[q * 3 + 1], qz = Qp[q * 3 + 2];
    const float ax = -2.0f * qx, ay = -2.0f * qy, az = -2.0f * qz;
    const float q2 = qx * qx + qy * qy + qz * qz;

    float m = CUDART_INF_F;
    const int t0 = stripe * (V / PSTRIPES);
    #pragma unroll 4
    for (int j = 0; j < V / PSTRIPES; j++) {
        const int g = t0 + j;
        const float tx = Tp[g * 3 + 0];
        const float ty = Tp[g * 3 + 1];
        const float tz = Tp[g * 3 + 2];
        const float w  = tx * tx + ty * ty + tz * tz;
        const float v  = fmaf(ax, tx, fmaf(ay, ty, fmaf(az, tz, w)));
        m = fminf(m, v);
    }

    __shared__ float sm[THREADS];
    sm[tid] = m;
    __syncthreads();
    if (stripe == 0) {
        const float mm = fminf(fminf(sm[qi], sm[qi + 64]),
                               fminf(sm[qi + 128], sm[qi + 192]));
        sm[qi] = fmaxf(q2 + mm, 0.0f);   // exact NN^2 for this pilot query
    }
    __syncthreads();
    if (tid == 0) {
        float L = 0.0f;
        #pragma unroll
        for (int i = 0; i < PQ; i++) L = fmaxf(L, sm[i]);
        atomicMax(&g_L[b], __float_as_uint(L));   // nonneg: uint order == float order
    }
}

// ---- Main: full scan with warp-level early exit against L_b. ----
__global__ void __launch_bounds__(THREADS, 1)
hd_main_kernel(const float* __restrict__ X, const float* __restrict__ Y) {
    __shared__ float4 sT[TS];
    __shared__ float wmax[THREADS / 32];

    const int b   = blockIdx.y;
    const int dir = blockIdx.z;
    const float* __restrict__ Qp = (dir == 0 ? X : Y) + (size_t)b * V * 3;
    const float* __restrict__ Tp = (dir == 0 ? Y : X) + (size_t)b * V * 3;

    const int tid = threadIdx.x;
    const int q0 = blockIdx.x * QPB + tid;
    const int q1 = q0 + THREADS;

    const float q0x = Qp[q0 * 3 + 0], q0y = Qp[q0 * 3 + 1], q0z = Qp[q0 * 3 + 2];
    const float q1x = Qp[q1 * 3 + 0], q1y = Qp[q1 * 3 + 1], q1z = Qp[q1 * 3 + 2];
    const float a0x = -2.0f * q0x, a0y = -2.0f * q0y, a0z = -2.0f * q0z;
    const float a1x = -2.0f * q1x, a1y = -2.0f * q1y, a1z = -2.0f * q1z;
    const float q2_0 = q0x * q0x + q0y * q0y + q0z * q0z;
    const float q2_1 = q1x * q1x + q1y * q1y + q1z * q1z;

    // Prune thresholds: (q2 + m < L) <=> (m < L - q2).
    const float L  = __uint_as_float(g_L[b]);
    const float l0 = L - q2_0;
    const float l1 = L - q2_1;

    float m0 = CUDART_INF_F;
    float m1 = CUDART_INF_F;
    bool done = false;

    #pragma unroll
    for (int t = 0; t < V / TS; t++) {
        __syncthreads();
        for (int i = tid; i < TS; i += THREADS) {
            const int g = t * TS + i;
            const float tx = Tp[g * 3 + 0];
            const float ty = Tp[g * 3 + 1];
            const float tz = Tp[g * 3 + 2];
            sT[i] = make_float4(tx, ty, tz, tx * tx + ty * ty + tz * tz);
        }
        __syncthreads();

        if (!done) {
            for (int jb = 0; jb < TS; jb += 32) {
                #pragma unroll 8
                for (int j = jb; j < jb + 32; j++) {
                    const float4 p = sT[j];   // broadcast LDS.128
                    const float v0 = fmaf(a0x, p.x, fmaf(a0y, p.y, fmaf(a0z, p.z, p.w)));
                    const float v1 = fmaf(a1x, p.x, fmaf(a1y, p.y, fmaf(a1z, p.z, p.w)));
                    m0 = fminf(m0, v0);
                    m1 = fminf(m1, v1);
                }
                // Warp exits when every lane's BOTH queries are provably
                // below the lower bound (can't be the Hausdorff argmax).
                if (__all_sync(0xffffffffu, (m0 < l0) && (m1 < l1))) {
                    done = true;
                    break;
                }
            }
        }
        // Skip remaining tiles if the whole CTA is done (uniform).
        if (__syncthreads_and((int)done)) break;
    }

    // Survivors hold exact full mins; pruned threads contribute 0 (safe: their
    // true NN^2 < L <= answer).
    float m = 0.0f;
    if (!done) {
        const float s0 = fmaxf(q2_0 + m0, 0.0f);
        const float s1 = fmaxf(q2_1 + m1, 0.0f);
        m = fmaxf(s0, s1);
    }

    #pragma unroll
    for (int off = 16; off > 0; off >>= 1)
        m = fmaxf(m, __shfl_xor_sync(0xffffffffu, m, off));
    if ((tid & 31) == 0) wmax[tid >> 5] = m;
    __syncthreads();

    if (tid == 0) {
        float mm = wmax[0];
        #pragma unroll
        for (int w = 1; w < THREADS / 32; w++) mm = fmaxf(mm, wmax[w]);
        atomicMax(&g_max[b], __float_as_uint(mm));
    }
}

__global__ void hd_final_kernel(float* __restrict__ out) {
    if (threadIdx.x == 0) {
        float s = 0.0f;
        #pragma unroll
        for (int i = 0; i < NB; i++) {
            // Seed with L_b: the pilot witness value (== some query's exact NN^2).
            const float v = fmaxf(__uint_as_float(g_max[i]), __uint_as_float(g_L[i]));
            s += sqrtf(v);
        }
        out[0] = s * (1.0f / (float)NB);   // LOSS_WEIGHT = 1.0
    }
}

extern "C" void kernel_launch(void* const* d_in, const int* in_sizes, int n_in,
                              void* d_out, int out_size) {
    const float* x = (const float*)d_in[0];
    const float* y = (const float*)d_in[1];
    float* out = (float*)d_out;

    hd_init_kernel<<<1, 32>>>();
    dim3 pgrid(2, NB);
    hd_pilot_kernel<<<pgrid, THREADS>>>(x, y);
    dim3 grid(CHUNKS, NB, 2);
    hd_main_kernel<<<grid, THREADS>>>(x, y);
    hd_final_kernel<<<1, 32>>>(out);
}

// round 6
// speedup vs baseline: 2.1411x; 2.1411x over previous
#include <cuda_runtime.h>
#include <math_constants.h>

// Hausdorff loss: x,y (8, 4096, 3) fp32 -> scalar.
// |q-t|^2 = |q|^2 + (|t|^2 - 2 q.t); min/max on squared values, sqrt at the end.
//
// Decomposition for perfect 148-SM balance: 148 = 4 * 37.
// Work unit = (dir, b, target-chunk), 2*8*37 = 592 CTAs = exactly 4 per SM,
// all resident in one wave (256 thr, ~2KB smem). Each CTA scans ALL 4096
// queries of its (dir,b) against its ~111-target chunk; per-query partial
// mins merge via atomicMin (REDG) into a 256KB device scratch.

#define NB 8
#define V  4096
#define TC 37                  // target chunks; 2*8*37 = 592 CTAs = 148*4
#define THREADS 256
#define NPASS (V / (2 * THREADS))   // 8 query passes, 2 queries/thread/pass
#define TMAX 111                    // max targets per chunk: ceil(4096/37)

__device__ unsigned g_minsq[2 * NB * V];  // per (dir,b,query) NN^2 bits
__device__ unsigned g_max[NB];
__device__ unsigned g_done;

__global__ void hd_init_kernel() {
    const int i = blockIdx.x * blockDim.x + threadIdx.x;
    if (i < 2 * NB * V) g_minsq[i] = 0x7F800000u;   // +inf
    if (i < NB) g_max[i] = 0u;
    if (i == 0) g_done = 0u;
}

__global__ void __launch_bounds__(THREADS)
hd_main_kernel(const float* __restrict__ X, const float* __restrict__ Y) {
    __shared__ float4 sT[TMAX];

    const int tc  = blockIdx.x;          // 0..36
    const int b   = blockIdx.y;
    const int dir = blockIdx.z;
    const float* __restrict__ Qp = (dir == 0 ? X : Y) + (size_t)b * V * 3;
    const float* __restrict__ Tp = (dir == 0 ? Y : X) + (size_t)b * V * 3;
    unsigned* __restrict__ slab = g_minsq + ((size_t)dir * NB + b) * V;

    const int t0 = (tc * V) / TC;
    const int t1 = ((tc + 1) * V) / TC;
    const int nt = t1 - t0;              // 110 or 111

    const int tid = threadIdx.x;

    // Load this chunk's targets once: (x, y, z, |t|^2).
    if (tid < nt) {
        const int g = t0 + tid;
        const float tx = Tp[g * 3 + 0];
        const float ty = Tp[g * 3 + 1];
        const float tz = Tp[g * 3 + 2];
        sT[tid] = make_float4(tx, ty, tz, tx * tx + ty * ty + tz * tz);
    }
    __syncthreads();

    #pragma unroll 1
    for (int p = 0; p < NPASS; p++) {
        const int q0 = p * (2 * THREADS) + tid;
        const int q1 = q0 + THREADS;

        const float q0x = Qp[q0 * 3 + 0], q0y = Qp[q0 * 3 + 1], q0z = Qp[q0 * 3 + 2];
        const float q1x = Qp[q1 * 3 + 0], q1y = Qp[q1 * 3 + 1], q1z = Qp[q1 * 3 + 2];
        const float a0x = -2.0f * q0x, a0y = -2.0f * q0y, a0z = -2.0f * q0z;
        const float a1x = -2.0f * q1x, a1y = -2.0f * q1y, a1z = -2.0f * q1z;
        const float q2_0 = q0x * q0x + q0y * q0y + q0z * q0z;
        const float q2_1 = q1x * q1x + q1y * q1y + q1z * q1z;

        float m0 = CUDART_INF_F, m1 = CUDART_INF_F;

        #pragma unroll 4
        for (int j = 0; j < nt; j++) {
            const float4 t = sT[j];   // broadcast LDS.128
            const float v0 = fmaf(a0x, t.x, fmaf(a0y, t.y, fmaf(a0z, t.z, t.w)));
            const float v1 = fmaf(a1x, t.x, fmaf(a1y, t.y, fmaf(a1z, t.z, t.w)));
            m0 = fminf(m0, v0);
            m1 = fminf(m1, v1);
        }

        const float s0 = fmaxf(q2_0 + m0, 0.0f);
        const float s1 = fmaxf(q2_1 + m1, 0.0f);
        // Nonnegative floats: uint ordering == float ordering.
        atomicMin(&slab[q0], __float_as_uint(s0));
        atomicMin(&slab[q1], __float_as_uint(s1));
    }
}

// 16 CTAs: CTA r reduces slab (dir = r>>3, b = r&7) -> atomicMax g_max[b].
// Last CTA to finish computes the final scalar.
__global__ void __launch_bounds__(THREADS)
hd_reduce_kernel(float* __restrict__ out) {
    __shared__ float wmax[THREADS / 32];
    const int r = blockIdx.x;
    const unsigned* __restrict__ slab = g_minsq + (size_t)r * V;
    const int tid = threadIdx.x;

    float m = 0.0f;
    #pragma unroll
    for (int i = tid; i < V; i += THREADS)
        m = fmaxf(m, __uint_as_float(slab[i]));

    #pragma unroll
    for (int off = 16; off > 0; off >>= 1)
        m = fmaxf(m, __shfl_xor_sync(0xffffffffu, m, off));
    if ((tid & 31) == 0) wmax[tid >> 5] = m;
    __syncthreads();

    if (tid == 0) {
        float mm = wmax[0];
        #pragma unroll
        for (int w = 1; w < THREADS / 32; w++) mm = fmaxf(mm, wmax[w]);
        atomicMax(&g_max[r & (NB - 1)], __float_as_uint(mm));

        __threadfence();
        const unsigned prev = atomicAdd(&g_done, 1u);
        if (prev == 2 * NB - 1) {          // last CTA: finalize
            float s = 0.0f;
            #pragma unroll
            for (int i = 0; i < NB; i++)
                s += sqrtf(__uint_as_float(g_max[i]));
            out[0] = s * (1.0f / (float)NB);   // LOSS_WEIGHT = 1.0
        }
    }
}

extern "C" void kernel_launch(void* const* d_in, const int* in_sizes, int n_in,
                              void* d_out, int out_size) {
    const float* x = (const float*)d_in[0];
    const float* y = (const float*)d_in[1];
    float* out = (float*)d_out;

    hd_init_kernel<<<(2 * NB * V + THREADS - 1) / THREADS, THREADS>>>();
    dim3 grid(TC, NB, 2);
    hd_main_kernel<<<grid, THREADS>>>(x, y);
    hd_reduce_kernel<<<2 * NB, THREADS>>>(out);
}